// round 5
// baseline (speedup 1.0000x reference)
#include <cuda_runtime.h>
#include <math.h>

#define B 96
#define D 512
#define RPB 4                 // rows of the dist matrix per block
#define GX (B / RPB)          // 24
#define GY 3                  // 32 columns per block-y
#define NBLK (GX * GY)        // 72 blocks
#define SDP 97                // padded row stride for shared dist (bank-conflict-free columns)

// ---------------- device scratch (no allocations allowed) ----------------
__device__ float        g_dist[B * B];
__device__ unsigned int g_count = 0;

__global__ __launch_bounds__(1024, 1)
void k_fused(const float* __restrict__ embs, const int* __restrict__ raw_idtys,
             float* __restrict__ out) {
    __shared__ float4   srow[RPB * (D / 4)];   // 8 KB: staged A-rows
    __shared__ float    s_ni[RPB];             // norms of staged rows
    __shared__ float    sd[B * SDP];           // 36.4 KB: full dist matrix (epilogue)
    __shared__ int      sy[B];
    __shared__ float    s_trip[B], s_ipart[B];
    __shared__ int      s_pos[B], s_neg[B];
    __shared__ int      s_bad;
    __shared__ unsigned s_ticket;

    const int tid  = threadIdx.x;
    const int w    = tid >> 5;
    const int lane = tid & 31;
    const int i0   = blockIdx.x * RPB;

    // ---- stage RPB embedding rows ----
    if (tid < RPB * (D / 4)) {
        int r = tid >> 7, c = tid & 127;
        srow[tid] = ((const float4*)(embs + (size_t)(i0 + r) * D))[c];
    }
    __syncthreads();

    // ---- norms of staged rows (warps 0..RPB-1) ----
    if (w < RPB) {
        float acc = 0.0f;
#pragma unroll
        for (int c = 0; c < 4; c++) {
            float4 a = srow[w * 128 + lane + 32 * c];
            acc += a.x * a.x + a.y * a.y + a.z * a.z + a.w * a.w;
        }
#pragma unroll
        for (int o = 16; o; o >>= 1) acc += __shfl_xor_sync(0xffffffffu, acc, o);
        if (lane == 0) s_ni[w] = acc;
    }
    __syncthreads();

    // ---- dot products: warp w owns column j, 4 rows each ----
    {
        const int j = blockIdx.y * 32 + w;
        const float4* rj = (const float4*)(embs + (size_t)j * D);
        float s0 = 0.f, s1 = 0.f, s2 = 0.f, s3 = 0.f, nj = 0.f;
#pragma unroll
        for (int c = 0; c < 4; c++) {
            float4 b  = rj[lane + 32 * c];
            nj += b.x * b.x + b.y * b.y + b.z * b.z + b.w * b.w;
            float4 a0 = srow[  0 + lane + 32 * c];
            float4 a1 = srow[128 + lane + 32 * c];
            float4 a2 = srow[256 + lane + 32 * c];
            float4 a3 = srow[384 + lane + 32 * c];
            s0 += a0.x * b.x + a0.y * b.y + a0.z * b.z + a0.w * b.w;
            s1 += a1.x * b.x + a1.y * b.y + a1.z * b.z + a1.w * b.w;
            s2 += a2.x * b.x + a2.y * b.y + a2.z * b.z + a2.w * b.w;
            s3 += a3.x * b.x + a3.y * b.y + a3.z * b.z + a3.w * b.w;
        }
#pragma unroll
        for (int o = 16; o; o >>= 1) {
            s0 += __shfl_xor_sync(0xffffffffu, s0, o);
            s1 += __shfl_xor_sync(0xffffffffu, s1, o);
            s2 += __shfl_xor_sync(0xffffffffu, s2, o);
            s3 += __shfl_xor_sync(0xffffffffu, s3, o);
            nj += __shfl_xor_sync(0xffffffffu, nj, o);
        }
        if (lane < RPB) {
            float s = (lane == 0) ? s0 : (lane == 1) ? s1 : (lane == 2) ? s2 : s3;
            int   i = i0 + lane;
            float v = fmaxf(s_ni[lane] + nj - 2.0f * s, 0.0f);   // ref: sq_j - 2 dot + sq_i, clamped
            float dres = (i == j || v <= 0.0f) ? 0.0f : sqrtf(v); // ref zero-handling
            g_dist[i * B + j] = dres;
        }
    }

    // ---- grid sync: last-arriving block runs the epilogue ----
    __threadfence();                 // every thread releases its dist writes to gpu scope
    __syncthreads();
    if (tid == 0) s_ticket = atomicAdd(&g_count, 1u);
    __syncthreads();
    if (s_ticket != NBLK - 1) return;
    if (tid == 0) g_count = 0;       // reset for next graph replay (all others finished)
    __threadfence();                 // acquire side before reading peer blocks' writes

    // ================= EPILOGUE (last block only, 1024 threads) =================

    // identity decode: int64-LE vs int32 autodetect
    if (tid == 0) s_bad = 0;
    __syncthreads();
    if (tid < 48) {
        int lo = raw_idtys[2 * tid];
        int hi = raw_idtys[2 * tid + 1];
        if (hi != 0 || (unsigned)lo >= 16u) s_bad = 1;   // benign race, same value
    }
    __syncthreads();
    if (tid < B) sy[tid] = s_bad ? raw_idtys[tid] : raw_idtys[2 * tid];

    // stage the full dist matrix into padded shared (L1-bypassing loads)
    for (int idx = tid; idx < B * B; idx += 1024) {
        int i = idx / B, j = idx - i * B;
        sd[i * SDP + j] = __ldcg(g_dist + idx);
    }
    __syncthreads();

    // ---- batch-hard mining: warp w handles rows w, w+32, w+64 ----
#pragma unroll
    for (int rq = 0; rq < 3; rq++) {
        const int i  = w + 32 * rq;
        const int yi = sy[i];
        float dv[3]; int yv[3];
#pragma unroll
        for (int q = 0; q < 3; q++) {
            int j = lane + 32 * q;
            dv[q] = sd[i * SDP + j];
            yv[q] = sy[j];
        }
        // row max (unmasked) for the an_dist offset
        float maxd = fmaxf(fmaxf(dv[0], dv[1]), dv[2]);
#pragma unroll
        for (int o = 16; o; o >>= 1)
            maxd = fmaxf(maxd, __shfl_xor_sync(0xffffffffu, maxd, o));

        // hardest positive: argmax over mask_ap*d, first-occurrence ties
        float pbest = -1.0f; int pidx = 1 << 20;
#pragma unroll
        for (int q = 0; q < 3; q++) {
            int j = lane + 32 * q;
            float apv = (j != i && yv[q] == yi) ? dv[q] : 0.0f;
            if (apv > pbest) { pbest = apv; pidx = j; }
        }
#pragma unroll
        for (int o = 16; o; o >>= 1) {
            float ov = __shfl_xor_sync(0xffffffffu, pbest, o);
            int   oi = __shfl_xor_sync(0xffffffffu, pidx, o);
            if (ov > pbest || (ov == pbest && oi < pidx)) { pbest = ov; pidx = oi; }
        }

        // hardest negative: argmin over d + maxd*(1-mask_an), first-occurrence ties
        float nbest = 3.4e38f; int nidx = 1 << 20;
#pragma unroll
        for (int q = 0; q < 3; q++) {
            int j = lane + 32 * q;
            float anv = (yv[q] != yi) ? dv[q] : dv[q] + maxd;
            if (anv < nbest) { nbest = anv; nidx = j; }
        }
#pragma unroll
        for (int o = 16; o; o >>= 1) {
            float ov = __shfl_xor_sync(0xffffffffu, nbest, o);
            int   oi = __shfl_xor_sync(0xffffffffu, nidx, o);
            if (ov < nbest || (ov == nbest && oi < nidx)) { nbest = ov; nidx = oi; }
        }

        if (lane == 0) {
            s_trip[i] = fmaxf(pbest - nbest + 0.2f, 0.0f);
            s_pos[i]  = pidx;
            s_neg[i]  = nidx;
        }
    }
    __syncthreads();

    // ---- inter-class term (factorized): warp w handles a = w, w+32, w+64 ----
#pragma unroll
    for (int rq = 0; rq < 3; rq++) {
        const int a = w + 32 * rq;
        const int p = s_pos[a], n = s_neg[a];
        const int yp = sy[p],   yn = sy[n];

        float M = -1.0f;   // stays -1 iff no valid b
#pragma unroll
        for (int q = 0; q < 3; q++) {
            int b = lane + 32 * q;
            if (b != p && sy[b] == yp) M = fmaxf(M, sd[b * SDP + p]);  // stride-97: no conflicts
        }
#pragma unroll
        for (int o = 16; o; o >>= 1)
            M = fmaxf(M, __shfl_xor_sync(0xffffffffu, M, o));

        float s = 0.0f;
        if (M >= 0.0f && yp != yn) {
#pragma unroll
            for (int q = 0; q < 3; q++) {
                int l  = lane + 32 * q;
                int yl = sy[l];
                if (yl != yp && yl != yn)
                    s += fmaxf(M - sd[n * SDP + l] + 0.1f, 0.0f);
            }
        }
#pragma unroll
        for (int o = 16; o; o >>= 1) s += __shfl_xor_sync(0xffffffffu, s, o);
        if (lane == 0) s_ipart[a] = s;
    }
    __syncthreads();

    // ---- final reduce: mean(trip) + mean_{a,l}(inter), fixed deterministic order ----
    if (w == 0) {
        float acc = 0.0f;
#pragma unroll
        for (int q = 0; q < 3; q++) {
            int t = lane + 32 * q;
            acc += s_trip[t] * (1.0f / B) + s_ipart[t] * (1.0f / (96.0f * 96.0f));
        }
#pragma unroll
        for (int o = 16; o; o >>= 1) acc += __shfl_xor_sync(0xffffffffu, acc, o);
        if (lane == 0) out[0] = acc;
    }
}

// ---------------------------------------------------------------------------
extern "C" void kernel_launch(void* const* d_in, const int* in_sizes, int n_in,
                              void* d_out, int out_size) {
    (void)in_sizes; (void)n_in; (void)out_size;
    const float* embs = (const float*)d_in[0];
    const int*   idt  = (const int*)d_in[1];   // int32 view; layout autodetected
    float*       out  = (float*)d_out;

    k_fused<<<dim3(GX, GY), 1024>>>(embs, idt, out);
}